// round 12
// baseline (speedup 1.0000x reference)
#include <cuda_runtime.h>

// LossFunction: fused IoU + smooth-L1 multi-loss over (B=256, N=8192, F=13).
//
// R12 = R11 resubmitted (previous round was a container/infra failure, the
// kernel never ran). Single-pass (R10: traffic 222MB confirmed) with LDG.256
// strips: each thread owns 8 consecutive rows = 104 floats = 13 aligned v8
// chunks per tensor. R10 was L1tex-wavefront-limited (~16B/wavefront with
// scattered LDG.128 -> ~4.8TB/s); 32B accesses double bytes/wavefront ->
// ceiling ~7.5TB/s. Feature identity compile-time; IoU computed eagerly.

#define F 13
#define THREADS 256
#define ROWS_PER_THREAD 8
#define ROWS_TILE (THREADS * ROWS_PER_THREAD)   // 2048
#define MAX_BLOCKS 4096

__device__ float        g_partials[MAX_BLOCKS];
__device__ unsigned int g_ticket = 0;

__device__ __forceinline__ float huber(float a, float b) {
    float d = fabsf(a - b);
    return d < 1.0f ? 0.5f * d * d : d - 0.5f;
}

__device__ __forceinline__ void ldg8(const float* p, float (&v)[8]) {
    unsigned r0, r1, r2, r3, r4, r5, r6, r7;
    asm("ld.global.nc.v8.b32 {%0,%1,%2,%3,%4,%5,%6,%7}, [%8];"
        : "=r"(r0), "=r"(r1), "=r"(r2), "=r"(r3),
          "=r"(r4), "=r"(r5), "=r"(r6), "=r"(r7)
        : "l"(p));
    v[0] = __uint_as_float(r0); v[1] = __uint_as_float(r1);
    v[2] = __uint_as_float(r2); v[3] = __uint_as_float(r3);
    v[4] = __uint_as_float(r4); v[5] = __uint_as_float(r5);
    v[6] = __uint_as_float(r6); v[7] = __uint_as_float(r7);
}

__global__ __launch_bounds__(THREADS, 3)
void loss_kernel(const float* __restrict__ tg,
                 const float* __restrict__ pr,
                 float* __restrict__ out,
                 long long rows,
                 float c1, float w2, float w4, float w3) {
    long long tile0 = (long long)blockIdx.x * ROWS_TILE;
    long long rem   = rows - tile0;
    int nrows = rem < ROWS_TILE ? (int)rem : ROWS_TILE;

    float acc = 0.0f;

    if (nrows == ROWS_TILE) {
        // Thread t owns rows tile0 + 8t .. 8t+7 : 104 floats = 13 v8 chunks,
        // strip base = 416B-multiple -> every chunk 32B aligned.
        long long r0 = tile0 + (long long)threadIdx.x * ROWS_PER_THREAD;
        const float* tstrip = tg + r0 * F;
        const float* pstrip = pr + r0 * F;

        float tb[ROWS_PER_THREAD][4], pb[ROWS_PER_THREAD][4];
        float a0 = 0.0f, a1 = 0.0f;

        #pragma unroll
        for (int c = 0; c < 13; c++) {
            float tv[8], pv[8];
            ldg8(tstrip + c * 8, tv);
            ldg8(pstrip + c * 8, pv);

            #pragma unroll
            for (int j = 0; j < 8; j++) {
                const int g = 8 * c + j;        // 0..103, compile-time
                const int r = g / 13;           // row within strip
                const int f = g - 13 * r;       // feature index
                float wgt = (f < 4) ? w2 : ((f < 12) ? w4 : w3);
                if (j & 1) a1 += wgt * huber(tv[j], pv[j]);
                else       a0 += wgt * huber(tv[j], pv[j]);
                if (f < 4) { tb[r][f] = tv[j]; pb[r][f] = pv[j]; }
            }

            // Eager IoU: row r's box completes at chunk containing float 13r+3.
            #pragma unroll
            for (int r = 0; r < ROWS_PER_THREAD; r++) {
                if ((13 * r + 3) / 8 == c) {    // compile-time predicate
                    float xx1 = fmaxf(tb[r][0], pb[r][0]);
                    float yy1 = fmaxf(tb[r][1], pb[r][1]);
                    float xx2 = fminf(tb[r][2], pb[r][2]);
                    float yy2 = fminf(tb[r][3], pb[r][3]);
                    float w = fmaxf(xx2 - xx1, 0.0f);
                    float h = fmaxf(yy2 - yy1, 0.0f);
                    float inter = w * h;
                    float area1 = (tb[r][2] - tb[r][0]) * (tb[r][3] - tb[r][1]);
                    float area2 = (pb[r][2] - pb[r][0]) * (pb[r][3] - pb[r][1]);
                    float iou = inter / (area1 + area2 - inter + 1e-7f);
                    acc += c1 * huber(1.0f, iou);
                }
            }
        }
        acc += a0 + a1;
    } else {
        // Generic tail tile (not hit for the benchmark shape).
        for (int r = threadIdx.x; r < nrows; r += THREADS) {
            const float* tr = tg + (tile0 + r) * F;
            const float* pq = pr + (tile0 + r) * F;
            float t[F], p[F];
            #pragma unroll
            for (int f = 0; f < F; f++) { t[f] = __ldg(tr + f); p[f] = __ldg(pq + f); }
            #pragma unroll
            for (int f = 0; f < F; f++) {
                float wgt = (f < 4) ? w2 : ((f < 12) ? w4 : w3);
                acc += wgt * huber(t[f], p[f]);
            }
            float xx1 = fmaxf(t[0], p[0]);
            float yy1 = fmaxf(t[1], p[1]);
            float xx2 = fminf(t[2], p[2]);
            float yy2 = fminf(t[3], p[3]);
            float w = fmaxf(xx2 - xx1, 0.0f);
            float h = fmaxf(yy2 - yy1, 0.0f);
            float inter = w * h;
            float area1 = (t[2] - t[0]) * (t[3] - t[1]);
            float area2 = (p[2] - p[0]) * (p[3] - p[1]);
            float iou = inter / (area1 + area2 - inter + 1e-7f);
            acc += c1 * huber(1.0f, iou);
        }
    }

    // ---- Block reduction ----
    #pragma unroll
    for (int off = 16; off > 0; off >>= 1)
        acc += __shfl_xor_sync(0xFFFFFFFFu, acc, off);

    __shared__ float warp_part[THREADS / 32];
    __shared__ bool  is_last;
    int lane = threadIdx.x & 31;
    int wid  = threadIdx.x >> 5;
    if (lane == 0) warp_part[wid] = acc;
    __syncthreads();

    if (wid == 0) {
        float v = lane < (THREADS / 32) ? warp_part[lane] : 0.0f;
        #pragma unroll
        for (int off = 4; off > 0; off >>= 1)
            v += __shfl_xor_sync(0xFFFFFFFFu, v, off);
        if (lane == 0) {
            g_partials[blockIdx.x] = v;
            __threadfence();
            unsigned t = atomicAdd(&g_ticket, 1u);
            is_last = (t == gridDim.x - 1);
        }
    }
    __syncthreads();

    // Last block reduces all partials (deterministic order) and writes out.
    if (is_last) {
        __threadfence();
        float v = 0.0f;
        for (int i = threadIdx.x; i < (int)gridDim.x; i += THREADS)
            v += g_partials[i];
        #pragma unroll
        for (int off = 16; off > 0; off >>= 1)
            v += __shfl_xor_sync(0xFFFFFFFFu, v, off);
        if (lane == 0) warp_part[wid] = v;
        __syncthreads();
        if (wid == 0) {
            float s = lane < (THREADS / 32) ? warp_part[lane] : 0.0f;
            #pragma unroll
            for (int off = 4; off > 0; off >>= 1)
                s += __shfl_xor_sync(0xFFFFFFFFu, s, off);
            if (lane == 0) {
                out[0] = s;
                g_ticket = 0;   // reset for next graph replay
            }
        }
    }
}

extern "C" void kernel_launch(void* const* d_in, const int* in_sizes, int n_in,
                              void* d_out, int out_size) {
    const float* targets = (const float*)d_in[0];
    const float* preds   = (const float*)d_in[1];
    float* out = (float*)d_out;

    long long total = (long long)in_sizes[0];
    long long rows  = total / F;  // B*N = 2,097,152

    float inv = 1.0f / (float)rows;
    // Exact per-feature weights (selection is compile-time static):
    float w2 = inv * 0.25f;    // f in [0,4)  : loss2 mean over rows*4
    float w4 = inv * 0.0625f;  // f in [4,12) : 0.5 * mean over rows*8
    float w3 = inv;            // f == 12     : loss3 mean over rows
    float c1 = inv;            // loss1 mean

    int grid = (int)((rows + ROWS_TILE - 1) / ROWS_TILE);  // 1024
    if (grid > MAX_BLOCKS) grid = MAX_BLOCKS;  // safety (not hit for bench shape)

    loss_kernel<<<grid, THREADS>>>(targets, preds, out, rows, c1, w2, w4, w3);
}

// round 14
// speedup vs baseline: 1.1641x; 1.1641x over previous
#include <cuda_runtime.h>

// LossFunction: fused IoU + smooth-L1 multi-loss over (B=256, N=8192, F=13).
//
// R13: coalesced float4 single-pass (R3's 5.37TB/s pattern) with ZERO in-loop
// index math. THREADS=416=13*32, so q = tid + 416k keeps q%13 loop-invariant:
// per-thread feature ids, weights, box predicates and smem staging offsets are
// computed once; in-loop addresses advance by compile-time constants.
// Box features staged to 32KB smem for the IoU pass. Single kernel,
// ticket + last-block deterministic reduction.

#define F 13
#define THREADS 416            // 13 * 32
#define K_ITERS 8
#define ROWS_TILE 1024         // 4*416*8/13
#define NWARPS (THREADS / 32)  // 13
#define MAX_BLOCKS 4096

__device__ float        g_partials[MAX_BLOCKS];
__device__ unsigned int g_ticket = 0;

__device__ __forceinline__ float huber(float a, float b) {
    float d = fabsf(a - b);
    return d < 1.0f ? 0.5f * d * d : d - 0.5f;
}

__global__ __launch_bounds__(THREADS, 3)
void loss_kernel(const float* __restrict__ tg,
                 const float* __restrict__ pr,
                 float* __restrict__ out,
                 long long rows,
                 float c1, float w2, float w4, float w3) {
    // Box staging: sbox[row][0..3]=target box, [4..7]=pred box. 32KB.
    __shared__ __align__(16) float sbox[ROWS_TILE * 8];
    __shared__ float warp_part[NWARPS];
    __shared__ bool  is_last;

    long long tile_row0 = (long long)blockIdx.x * ROWS_TILE;
    long long rem       = rows - tile_row0;
    int nrows = rem < ROWS_TILE ? (int)rem : ROWS_TILE;

    int t = threadIdx.x;
    float acc = 0.0f;

    if (nrows == ROWS_TILE) {
        const float4* t4 = (const float4*)(tg + tile_row0 * F);
        const float4* p4 = (const float4*)(pr + tile_row0 * F);

        // ---- Loop-invariant per-thread constants (THREADS % 13 == 0) ----
        int e0 = 4 * t;
        int f_[4], rb_[4];
        float w_[4];
        bool b_[4];
        #pragma unroll
        for (int j = 0; j < 4; j++) {
            int e = e0 + j;
            rb_[j] = e / 13;              // row base within tile
            f_[j]  = e - 13 * rb_[j];     // feature index (invariant over k)
            w_[j]  = (f_[j] < 4) ? w2 : ((f_[j] < 12) ? w4 : w3);
            b_[j]  = (f_[j] < 4);
        }

        float a0 = 0.0f, a1 = 0.0f;
        #pragma unroll
        for (int k = 0; k < K_ITERS; k++) {
            float4 tv = __ldg(t4 + t + k * THREADS);
            float4 pv = __ldg(p4 + t + k * THREADS);
            float ta[4] = {tv.x, tv.y, tv.z, tv.w};
            float pa[4] = {pv.x, pv.y, pv.z, pv.w};
            int rowk = 128 * k;           // rows advance 128 per iteration
            #pragma unroll
            for (int j = 0; j < 4; j++) {
                if (j & 1) a1 += w_[j] * huber(ta[j], pa[j]);
                else       a0 += w_[j] * huber(ta[j], pa[j]);
                if (b_[j]) {              // invariant predicate
                    int base = (rb_[j] + rowk) * 8 + f_[j];
                    sbox[base]     = ta[j];
                    sbox[base + 4] = pa[j];
                }
            }
        }
        acc = a0 + a1;
    } else {
        // Generic tail tile (not hit for the benchmark shape).
        for (int r = t; r < nrows; r += THREADS) {
            const float* tr = tg + (tile_row0 + r) * F;
            const float* pq = pr + (tile_row0 + r) * F;
            #pragma unroll
            for (int f = 0; f < F; f++) {
                float wgt = (f < 4) ? w2 : ((f < 12) ? w4 : w3);
                float tv = __ldg(tr + f), pv = __ldg(pq + f);
                acc += wgt * huber(tv, pv);
                if (f < 4) {
                    sbox[r * 8 + f]     = tv;
                    sbox[r * 8 + 4 + f] = pv;
                }
            }
        }
    }
    __syncthreads();

    // ---- IoU pass from smem (conflict-free float4 LDS) ----
    for (int r = t; r < nrows; r += THREADS) {
        float4 tb = *(const float4*)&sbox[r * 8];
        float4 pb = *(const float4*)&sbox[r * 8 + 4];
        float xx1 = fmaxf(tb.x, pb.x);
        float yy1 = fmaxf(tb.y, pb.y);
        float xx2 = fminf(tb.z, pb.z);
        float yy2 = fminf(tb.w, pb.w);
        float w = fmaxf(xx2 - xx1, 0.0f);
        float h = fmaxf(yy2 - yy1, 0.0f);
        float inter = w * h;
        float area1 = (tb.z - tb.x) * (tb.w - tb.y);
        float area2 = (pb.z - pb.x) * (pb.w - pb.y);
        float iou = inter / (area1 + area2 - inter + 1e-7f);
        acc += c1 * huber(1.0f, iou);
    }

    // ---- Block reduction ----
    #pragma unroll
    for (int off = 16; off > 0; off >>= 1)
        acc += __shfl_xor_sync(0xFFFFFFFFu, acc, off);

    int lane = t & 31;
    int wid  = t >> 5;
    if (lane == 0) warp_part[wid] = acc;
    __syncthreads();

    if (wid == 0) {
        float v = lane < NWARPS ? warp_part[lane] : 0.0f;
        #pragma unroll
        for (int off = 8; off > 0; off >>= 1)
            v += __shfl_xor_sync(0xFFFFFFFFu, v, off);
        if (lane == 0) {
            g_partials[blockIdx.x] = v;
            __threadfence();
            unsigned tk = atomicAdd(&g_ticket, 1u);
            is_last = (tk == gridDim.x - 1);
        }
    }
    __syncthreads();

    // Last block reduces all partials (deterministic order) and writes out.
    if (is_last) {
        __threadfence();
        float v = 0.0f;
        for (int i = t; i < (int)gridDim.x; i += THREADS)
            v += g_partials[i];
        #pragma unroll
        for (int off = 16; off > 0; off >>= 1)
            v += __shfl_xor_sync(0xFFFFFFFFu, v, off);
        if (lane == 0) warp_part[wid] = v;
        __syncthreads();
        if (wid == 0) {
            float s = lane < NWARPS ? warp_part[lane] : 0.0f;
            #pragma unroll
            for (int off = 8; off > 0; off >>= 1)
                s += __shfl_xor_sync(0xFFFFFFFFu, s, off);
            if (lane == 0) {
                out[0] = s;
                g_ticket = 0;   // reset for next graph replay
            }
        }
    }
}

extern "C" void kernel_launch(void* const* d_in, const int* in_sizes, int n_in,
                              void* d_out, int out_size) {
    const float* targets = (const float*)d_in[0];
    const float* preds   = (const float*)d_in[1];
    float* out = (float*)d_out;

    long long total = (long long)in_sizes[0];
    long long rows  = total / F;  // B*N = 2,097,152

    float inv = 1.0f / (float)rows;
    // Exact per-feature weights:
    float w2 = inv * 0.25f;    // f in [0,4)  : loss2 mean over rows*4
    float w4 = inv * 0.0625f;  // f in [4,12) : 0.5 * mean over rows*8
    float w3 = inv;            // f == 12     : loss3 mean over rows
    float c1 = inv;            // loss1 mean

    int grid = (int)((rows + ROWS_TILE - 1) / ROWS_TILE);  // 2048 exact
    if (grid > MAX_BLOCKS) grid = MAX_BLOCKS;  // safety (not hit for bench shape)

    loss_kernel<<<grid, THREADS>>>(targets, preds, out, rows, c1, w2, w4, w3);
}